// round 2
// baseline (speedup 1.0000x reference)
#include <cuda_runtime.h>

#define B_    256
#define T_    250
#define DIN   700
#define H1N   256
#define H2N   256
#define DOUT  20
#define BJ0   0.01f
#define BETA_ 1.8f

#define SPC    64                       // samples per CTA in K1
#define TILE_D 128                      // weight rows per smem tile in K1
#define NT     ((DIN + TILE_D - 1) / TILE_D)   // 6

// Scratch (device globals — no allocations allowed)
__device__ float g_I1[B_ * T_ * H1N];          // x @ w_i2h1.T  (65.5 MB)
__device__ float g_Wt_i2h1[DIN * H1N];         // [d][j]
__device__ float g_Wt_h12h1[H1N * H1N];        // [k][j]
__device__ float g_Wt_h12h2[H1N * H2N];        // [k][j]
__device__ float g_Wt_h22h2[H2N * H2N];        // [k][j]
__device__ float g_Wt_h2o[H2N * DOUT];         // [k][o]

// ---------------------------------------------------------------------------
// K0: transpose weights to k-major (coalesced spike gathers)
// ---------------------------------------------------------------------------
__global__ void prep_kernel(const float* __restrict__ wi,
                            const float* __restrict__ w11,
                            const float* __restrict__ w12,
                            const float* __restrict__ w22,
                            const float* __restrict__ wo) {
    int idx = blockIdx.x * blockDim.x + threadIdx.x;
    if (idx < H1N * DIN) {
        int r = idx / DIN, c = idx % DIN;
        g_Wt_i2h1[c * H1N + r] = wi[idx];
    }
    if (idx < H1N * H1N) {
        int r = idx / H1N, c = idx % H1N;
        g_Wt_h12h1[c * H1N + r] = w11[idx];
        g_Wt_h12h2[c * H1N + r] = w12[idx];
        g_Wt_h22h2[c * H1N + r] = w22[idx];
    }
    if (idx < DOUT * H2N) {
        int r = idx / H2N, c = idx % H2N;
        g_Wt_h2o[c * DOUT + r] = wo[idx];
    }
}

// ---------------------------------------------------------------------------
// K1: input projection with smem weight tiles. One CTA = 64 samples.
// Per tile: load 128 weight rows to smem, build per-sample active lists,
// gather-sum from smem. Ascending-d summation order preserved exactly.
// smem: weights 128KB + accumulators 64KB + lists 16KB + counts.
// ---------------------------------------------------------------------------
__global__ __launch_bounds__(256, 1) void input_proj_kernel(const float* __restrict__ x) {
    extern __shared__ unsigned char smraw[];
    float*          Wt   = (float*)smraw;                                  // TILE_D*H1N
    float*          accs = (float*)(smraw + TILE_D * H1N * 4);             // SPC*H1N
    unsigned short* lst  = (unsigned short*)(smraw + TILE_D * H1N * 4 + SPC * H1N * 4);
    int*            cnt  = (int*)(smraw + TILE_D * H1N * 4 + SPC * H1N * 4 + SPC * TILE_D * 2);

    const int j    = threadIdx.x;
    const int warp = j >> 5;
    const int lane = j & 31;
    const int row0 = blockIdx.x * SPC;

    for (int s = 0; s < SPC; s++) accs[s * H1N + j] = 0.f;

    for (int tile = 0; tile < NT; tile++) {
        const int d0 = tile * TILE_D;
        const int dn = (DIN - d0 < TILE_D) ? (DIN - d0) : TILE_D;

        __syncthreads();   // previous tile fully consumed before overwrite

        // load weight tile, float4-coalesced
        {
            const float4* src = (const float4*)(g_Wt_i2h1 + (size_t)d0 * H1N);
            float4*       dst = (float4*)Wt;
            const int nv = dn * (H1N / 4);
            for (int idx = j; idx < nv; idx += 256) dst[idx] = src[idx];
        }

        // build per-sample active lists (warp w handles 8 samples)
        for (int s = warp * (SPC / 8); s < (warp + 1) * (SPC / 8); s++) {
            const float* xr = x + (size_t)(row0 + s) * DIN + d0;
            int c = 0;
            for (int bb = 0; bb < dn; bb += 32) {
                int d = bb + lane;
                float v = (d < dn) ? xr[d] : 0.f;
                unsigned m = __ballot_sync(0xffffffffu, v != 0.f);
                if (v != 0.f)
                    lst[s * TILE_D + c + __popc(m & ((1u << lane) - 1u))] = (unsigned short)d;
                c += __popc(m);
            }
            if (lane == 0) cnt[s] = c;
        }
        __syncthreads();

        // consume: gather-sum active rows from smem
        for (int s = 0; s < SPC; s++) {
            const int n = cnt[s];
            const unsigned short* ls = lst + s * TILE_D;
            float a = accs[s * H1N + j];
            int i = 0;
            for (; i + 4 <= n; i += 4) {
                float w0 = Wt[ls[i]     * H1N + j];
                float w1 = Wt[ls[i + 1] * H1N + j];
                float w2 = Wt[ls[i + 2] * H1N + j];
                float w3 = Wt[ls[i + 3] * H1N + j];
                a += w0; a += w1; a += w2; a += w3;
            }
            for (; i < n; i++) a += Wt[ls[i] * H1N + j];
            accs[s * H1N + j] = a;
        }
    }

    for (int s = 0; s < SPC; s++)
        g_I1[(size_t)(row0 + s) * H1N + j] = accs[s * H1N + j];
}

// ---------------------------------------------------------------------------
// K2 gather helpers: high-MLP (16-index blocks => 16/32 loads in flight),
// strictly ascending-index accumulation order.
// ---------------------------------------------------------------------------
__device__ __forceinline__ void gather_pair(const int* __restrict__ L, int n,
                                            const float* __restrict__ W1,
                                            const float* __restrict__ W2,
                                            int j, float& a1r, float& a2r) {
    float a1 = a1r, a2 = a2r;
    int i = 0;
    for (; i + 16 <= n; i += 16) {
        float u[16], v[16];
        #pragma unroll
        for (int r = 0; r < 16; r++) {
            int k = L[i + r];
            u[r] = W1[k * 256 + j];
            v[r] = W2[k * 256 + j];
        }
        #pragma unroll
        for (int r = 0; r < 16; r++) a1 += u[r];
        #pragma unroll
        for (int r = 0; r < 16; r++) a2 += v[r];
    }
    for (; i + 4 <= n; i += 4) {
        int k0 = L[i], k1 = L[i + 1], k2 = L[i + 2], k3 = L[i + 3];
        float u0 = W1[k0 * 256 + j], u1 = W1[k1 * 256 + j];
        float u2 = W1[k2 * 256 + j], u3 = W1[k3 * 256 + j];
        float v0 = W2[k0 * 256 + j], v1 = W2[k1 * 256 + j];
        float v2 = W2[k2 * 256 + j], v3 = W2[k3 * 256 + j];
        a1 += u0; a1 += u1; a1 += u2; a1 += u3;
        a2 += v0; a2 += v1; a2 += v2; a2 += v3;
    }
    for (; i < n; i++) { a1 += W1[L[i] * 256 + j]; a2 += W2[L[i] * 256 + j]; }
    a1r = a1; a2r = a2;
}

__device__ __forceinline__ void gather_one(const int* __restrict__ L, int n,
                                           const float* __restrict__ W1,
                                           int j, float& a1r) {
    float a1 = a1r;
    int i = 0;
    for (; i + 16 <= n; i += 16) {
        float u[16];
        #pragma unroll
        for (int r = 0; r < 16; r++) u[r] = W1[L[i + r] * 256 + j];
        #pragma unroll
        for (int r = 0; r < 16; r++) a1 += u[r];
    }
    for (; i + 4 <= n; i += 4) {
        float u0 = W1[L[i] * 256 + j],     u1 = W1[L[i + 1] * 256 + j];
        float u2 = W1[L[i + 2] * 256 + j], u3 = W1[L[i + 3] * 256 + j];
        a1 += u0; a1 += u1; a1 += u2; a1 += u3;
    }
    for (; i < n; i++) a1 += W1[L[i] * 256 + j];
    a1r = a1;
}

// ---------------------------------------------------------------------------
// K2: persistent recurrent kernel, pipelined. The w_h12h1 gather for step t+1
// is merged with the w_h12h2 gather of step t (same index list L1_t). The
// output gather is parallelized across all 8 warps (no feedback path).
// 5 syncthreads/step, 2 serial gather phases.
// ---------------------------------------------------------------------------
__global__ __launch_bounds__(256, 1) void recurrent_kernel(
    const float* __restrict__ b_h1g, const float* __restrict__ b_h2g,
    const float* __restrict__ b_og,
    const float* __restrict__ tau_adp_h1, const float* __restrict__ tau_adp_h2,
    const float* __restrict__ tau_m_h1,  const float* __restrict__ tau_m_h2,
    const float* __restrict__ tau_m_o,
    float* __restrict__ out) {

    const int b    = blockIdx.x;
    const int j    = threadIdx.x;
    const int warp = j >> 5;
    const int lane = j & 31;

    __shared__ int      L1[H1N], L2[H2N];
    __shared__ unsigned msk1[8], msk2[8];
    __shared__ float    part[8 * DOUT];

    const float alpha1 = expf(-1.f / tau_m_h1[j]);
    const float ro1    = expf(-1.f / tau_adp_h1[j]);
    const float alpha2 = expf(-1.f / tau_m_h2[j]);
    const float ro2    = expf(-1.f / tau_adp_h2[j]);
    const float bh1    = b_h1g[j];
    const float bh2    = b_h2g[j];

    float mem1 = 0.f, spk1 = 0.f, bb1 = BJ0;
    float mem2 = 0.f, spk2 = 0.f, bb2 = BJ0;

    float alpha_o = 0.f, bo = 0.f, mem_o = 0.f, acc_o = 0.f;
    if (j < DOUT) { alpha_o = expf(-1.f / tau_m_o[j]); bo = b_og[j]; }

    const float* I1row = g_I1 + (size_t)b * T_ * H1N;

    // s11 = (I1[t] + bh1) + sum_{L1_{t-1}} w11  — recurrent layer-1 drive
    float s11 = I1row[j] + bh1;     // t=0: no recurrent terms
    float s22 = 0.f;                // sum_{L2_{t-1}} w22
    int n1 = 0, n2 = 0;

    for (int t = 0; t < T_; t++) {
        // prefetch next step's input projection
        const int tn = (t + 1 < T_) ? (t + 1) : (T_ - 1);
        const float i1n = I1row[tn * H1N + j];

        // ---- layer 1 (h == s11, order identical to incremental sum)
        bb1  = ro1 * bb1 + BETA_ * (1.f - ro1) * spk1;
        mem1 = mem1 * alpha1 - bb1 * spk1 + (1.f - alpha1) * s11;
        spk1 = (mem1 - bb1 - BJ0 > 0.f) ? 1.f : 0.f;

        unsigned m1 = __ballot_sync(0xffffffffu, spk1 > 0.5f);
        if (lane == 0) msk1[warp] = m1;
        __syncthreads();                                   // A: masks visible
        {
            int off = 0, tot = 0;
            #pragma unroll
            for (int w = 0; w < 8; w++) {
                int c = __popc(msk1[w]);
                if (w < warp) off += c;
                tot += c;
            }
            if (spk1 > 0.5f) L1[off + __popc(m1 & ((1u << lane) - 1u))] = j;
            n1 = tot;
        }
        __syncthreads();                                   // B: L1 ready

        // ---- merged gather over L1_t: w11 -> s11 (for t+1), w12 -> h2 part
        float a1 = i1n + bh1;
        float a2 = bh2;
        gather_pair(L1, n1, g_Wt_h12h1, g_Wt_h12h2, j, a1, a2);
        s11 = a1;

        // ---- layer 2
        float h2 = a2 + s22;
        bb2  = ro2 * bb2 + BETA_ * (1.f - ro2) * spk2;
        mem2 = mem2 * alpha2 - bb2 * spk2 + (1.f - alpha2) * h2;
        spk2 = (mem2 - bb2 - BJ0 > 0.f) ? 1.f : 0.f;

        unsigned m2 = __ballot_sync(0xffffffffu, spk2 > 0.5f);
        if (lane == 0) msk2[warp] = m2;
        __syncthreads();                                   // C
        {
            int off = 0, tot = 0;
            #pragma unroll
            for (int w = 0; w < 8; w++) {
                int c = __popc(msk2[w]);
                if (w < warp) off += c;
                tot += c;
            }
            if (spk2 > 0.5f) L2[off + __popc(m2 & ((1u << lane) - 1u))] = j;
            n2 = tot;
        }
        __syncthreads();                                   // D: L2 ready

        // ---- gather over L2_t: w22 -> s22 (for t+1)
        float a3 = 0.f;
        gather_one(L2, n2, g_Wt_h22h2, j, a3);
        s22 = a3;

        // ---- output partials: warp w sums its ascending chunk of L2
        if (lane < DOUT) {
            float po = 0.f;
            const int i0 = (n2 * warp) >> 3;
            const int i1 = (n2 * (warp + 1)) >> 3;
            int i = i0;
            for (; i + 4 <= i1; i += 4) {
                float w0 = g_Wt_h2o[L2[i]     * DOUT + lane];
                float w1 = g_Wt_h2o[L2[i + 1] * DOUT + lane];
                float w2 = g_Wt_h2o[L2[i + 2] * DOUT + lane];
                float w3 = g_Wt_h2o[L2[i + 3] * DOUT + lane];
                po += w0; po += w1; po += w2; po += w3;
            }
            for (; i < i1; i++) po += g_Wt_h2o[L2[i] * DOUT + lane];
            part[warp * DOUT + lane] = po;
        }
        __syncthreads();                                   // E: partials ready

        if (warp == 0) {
            float oin = 0.f;
            if (lane < DOUT) {
                oin = bo;
                #pragma unroll
                for (int w = 0; w < 8; w++) oin += part[w * DOUT + lane];
            }
            mem_o = mem_o * alpha_o + (1.f - alpha_o) * oin;
            float vv = (lane < DOUT) ? mem_o : -1e30f;
            float mx = vv;
            #pragma unroll
            for (int s = 16; s > 0; s >>= 1)
                mx = fmaxf(mx, __shfl_xor_sync(0xffffffffu, mx, s));
            float e = (lane < DOUT) ? expf(vv - mx) : 0.f;
            float sm = e;
            #pragma unroll
            for (int s = 16; s > 0; s >>= 1)
                sm += __shfl_xor_sync(0xffffffffu, sm, s);
            if (lane < DOUT) acc_o += e / sm;
        }
    }

    if (j < DOUT) out[b * DOUT + j] = acc_o;
}

// ---------------------------------------------------------------------------
extern "C" void kernel_launch(void* const* d_in, const int* in_sizes, int n_in,
                              void* d_out, int out_size) {
    const float* x          = (const float*)d_in[0];
    const float* w_i2h1     = (const float*)d_in[1];
    const float* w_h12h1    = (const float*)d_in[2];
    const float* w_h12h2    = (const float*)d_in[3];
    const float* w_h22h2    = (const float*)d_in[4];
    const float* w_h2o      = (const float*)d_in[5];
    const float* b_h1       = (const float*)d_in[6];
    const float* b_h2       = (const float*)d_in[7];
    const float* b_o        = (const float*)d_in[8];
    const float* tau_adp_h1 = (const float*)d_in[9];
    const float* tau_adp_h2 = (const float*)d_in[10];
    const float* tau_m_h1   = (const float*)d_in[11];
    const float* tau_m_h2   = (const float*)d_in[12];
    const float* tau_m_o    = (const float*)d_in[13];

    const int k1_smem = TILE_D * H1N * 4 + SPC * H1N * 4 + SPC * TILE_D * 2 + SPC * 4;
    static bool attr_set = false;
    if (!attr_set) {
        cudaFuncSetAttribute(input_proj_kernel,
                             cudaFuncAttributeMaxDynamicSharedMemorySize, k1_smem);
        attr_set = true;
    }

    prep_kernel<<<(H1N * DIN + 255) / 256, 256>>>(w_i2h1, w_h12h1, w_h12h2,
                                                  w_h22h2, w_h2o);
    input_proj_kernel<<<(B_ * T_) / SPC, 256, k1_smem>>>(x);
    recurrent_kernel<<<B_, 256>>>(b_h1, b_h2, b_o,
                                  tau_adp_h1, tau_adp_h2,
                                  tau_m_h1, tau_m_h2, tau_m_o,
                                  (float*)d_out);
}

// round 3
// speedup vs baseline: 1.3231x; 1.3231x over previous
#include <cuda_runtime.h>

#define B_    256
#define T_    250
#define DIN   700
#define H1N   256
#define H2N   256
#define DOUT  20
#define BJ0   0.01f
#define BETA_ 1.8f

// Scratch (device globals — no allocations allowed)
__device__ float g_I1[B_ * T_ * H1N];          // x @ w_i2h1.T  (65.5 MB)
__device__ float g_Wt_i2h1[DIN * H1N];         // [d][j]
__device__ float g_Wt_h12h1[H1N * H1N];        // [k][j]
__device__ float g_Wt_h12h2[H1N * H2N];        // [k][j]
__device__ float g_Wt_h22h2[H2N * H2N];        // [k][j]
__device__ float g_Wt_h2o[H2N * DOUT];         // [k][o]

// ---------------------------------------------------------------------------
// K0: transpose weights to k-major (coalesced spike gathers)
// ---------------------------------------------------------------------------
__global__ void prep_kernel(const float* __restrict__ wi,
                            const float* __restrict__ w11,
                            const float* __restrict__ w12,
                            const float* __restrict__ w22,
                            const float* __restrict__ wo) {
    int idx = blockIdx.x * blockDim.x + threadIdx.x;
    if (idx < H1N * DIN) {
        int r = idx / DIN, c = idx % DIN;
        g_Wt_i2h1[c * H1N + r] = wi[idx];
    }
    if (idx < H1N * H1N) {
        int r = idx / H1N, c = idx % H1N;
        g_Wt_h12h1[c * H1N + r] = w11[idx];
        g_Wt_h12h2[c * H1N + r] = w12[idx];
        g_Wt_h22h2[c * H1N + r] = w22[idx];
    }
    if (idx < DOUT * H2N) {
        int r = idx / H2N, c = idx % H2N;
        g_Wt_h2o[c * DOUT + r] = wo[idx];
    }
}

// ---------------------------------------------------------------------------
// K1: input projection (R1 structure — known good). One CTA per (b,t) sample.
// x is binary -> gather-sum of active weight rows, ascending-d order.
// Unroll 8 for MLP.
// ---------------------------------------------------------------------------
__global__ __launch_bounds__(256) void input_proj_kernel(const float* __restrict__ x) {
    int row = blockIdx.x;          // b*T + t
    int j   = threadIdx.x;

    __shared__ int lst[DIN];
    __shared__ int nn;

    if (threadIdx.x < 32) {
        int lane = threadIdx.x;
        int cnt = 0;
        const float* xr = x + (size_t)row * DIN;
        for (int base = 0; base < DIN; base += 32) {
            int d = base + lane;
            float v = (d < DIN) ? xr[d] : 0.f;
            unsigned m = __ballot_sync(0xffffffffu, v != 0.f);
            if (v != 0.f)
                lst[cnt + __popc(m & ((1u << lane) - 1u))] = d;
            cnt += __popc(m);
        }
        if (lane == 0) nn = cnt;
    }
    __syncthreads();

    int n = nn;
    float acc = 0.f;
    int i = 0;
    for (; i + 8 <= n; i += 8) {
        float w0 = g_Wt_i2h1[lst[i]     * H1N + j];
        float w1 = g_Wt_i2h1[lst[i + 1] * H1N + j];
        float w2 = g_Wt_i2h1[lst[i + 2] * H1N + j];
        float w3 = g_Wt_i2h1[lst[i + 3] * H1N + j];
        float w4 = g_Wt_i2h1[lst[i + 4] * H1N + j];
        float w5 = g_Wt_i2h1[lst[i + 5] * H1N + j];
        float w6 = g_Wt_i2h1[lst[i + 6] * H1N + j];
        float w7 = g_Wt_i2h1[lst[i + 7] * H1N + j];
        acc += w0; acc += w1; acc += w2; acc += w3;
        acc += w4; acc += w5; acc += w6; acc += w7;
    }
    for (; i < n; i++) acc += g_Wt_i2h1[lst[i] * H1N + j];

    g_I1[(size_t)row * H1N + j] = acc;
}

// ---------------------------------------------------------------------------
// K2 gather helpers: 8-index blocks (16 loads in flight for pair),
// strictly ascending-index accumulation order per column.
// ---------------------------------------------------------------------------
__device__ __forceinline__ void gather_pair(const int* __restrict__ L, int n,
                                            const float* __restrict__ W1,
                                            const float* __restrict__ W2,
                                            int j, float& a1r, float& a2r) {
    float a1 = a1r, a2 = a2r;
    int i = 0;
    for (; i + 8 <= n; i += 8) {
        float u[8], v[8];
        #pragma unroll
        for (int r = 0; r < 8; r++) {
            int k = L[i + r];
            u[r] = W1[k * 256 + j];
            v[r] = W2[k * 256 + j];
        }
        #pragma unroll
        for (int r = 0; r < 8; r++) a1 += u[r];
        #pragma unroll
        for (int r = 0; r < 8; r++) a2 += v[r];
    }
    for (; i < n; i++) { a1 += W1[L[i] * 256 + j]; a2 += W2[L[i] * 256 + j]; }
    a1r = a1; a2r = a2;
}

__device__ __forceinline__ void gather_one(const int* __restrict__ L, int n,
                                           const float* __restrict__ W1,
                                           int j, float& a1r) {
    float a1 = a1r;
    int i = 0;
    for (; i + 8 <= n; i += 8) {
        float u[8];
        #pragma unroll
        for (int r = 0; r < 8; r++) u[r] = W1[L[i + r] * 256 + j];
        #pragma unroll
        for (int r = 0; r < 8; r++) a1 += u[r];
    }
    for (; i < n; i++) a1 += W1[L[i] * 256 + j];
    a1r = a1;
}

// ---------------------------------------------------------------------------
// K2: persistent recurrent kernel, pipelined. The w_h12h1 gather for step t+1
// is merged with the w_h12h2 gather of step t (same index list L1_t). The
// output gather is parallelized across all 8 warps (no feedback path).
// 5 syncthreads/step, 2 serial gather phases.
// ---------------------------------------------------------------------------
__global__ __launch_bounds__(256, 1) void recurrent_kernel(
    const float* __restrict__ b_h1g, const float* __restrict__ b_h2g,
    const float* __restrict__ b_og,
    const float* __restrict__ tau_adp_h1, const float* __restrict__ tau_adp_h2,
    const float* __restrict__ tau_m_h1,  const float* __restrict__ tau_m_h2,
    const float* __restrict__ tau_m_o,
    float* __restrict__ out) {

    const int b    = blockIdx.x;
    const int j    = threadIdx.x;
    const int warp = j >> 5;
    const int lane = j & 31;

    __shared__ int      L1[H1N], L2[H2N];
    __shared__ unsigned msk1[8], msk2[8];
    __shared__ float    part[8 * DOUT];

    const float alpha1 = expf(-1.f / tau_m_h1[j]);
    const float ro1    = expf(-1.f / tau_adp_h1[j]);
    const float alpha2 = expf(-1.f / tau_m_h2[j]);
    const float ro2    = expf(-1.f / tau_adp_h2[j]);
    const float bh1    = b_h1g[j];
    const float bh2    = b_h2g[j];

    float mem1 = 0.f, spk1 = 0.f, bb1 = BJ0;
    float mem2 = 0.f, spk2 = 0.f, bb2 = BJ0;

    float alpha_o = 0.f, bo = 0.f, mem_o = 0.f, acc_o = 0.f;
    if (j < DOUT) { alpha_o = expf(-1.f / tau_m_o[j]); bo = b_og[j]; }

    const float* I1row = g_I1 + (size_t)b * T_ * H1N;

    // s11 = (I1[t] + bh1) + sum_{L1_{t-1}} w11  — recurrent layer-1 drive
    float s11 = I1row[j] + bh1;     // t=0: no recurrent terms
    float s22 = 0.f;                // sum_{L2_{t-1}} w22
    int n1 = 0, n2 = 0;

    for (int t = 0; t < T_; t++) {
        // prefetch next step's input projection
        const int tn = (t + 1 < T_) ? (t + 1) : (T_ - 1);
        const float i1n = I1row[tn * H1N + j];

        // ---- layer 1 (h == s11, order identical to incremental sum)
        bb1  = ro1 * bb1 + BETA_ * (1.f - ro1) * spk1;
        mem1 = mem1 * alpha1 - bb1 * spk1 + (1.f - alpha1) * s11;
        spk1 = (mem1 - bb1 - BJ0 > 0.f) ? 1.f : 0.f;

        unsigned m1 = __ballot_sync(0xffffffffu, spk1 > 0.5f);
        if (lane == 0) msk1[warp] = m1;
        __syncthreads();                                   // A: masks visible
        {
            int off = 0, tot = 0;
            #pragma unroll
            for (int w = 0; w < 8; w++) {
                int c = __popc(msk1[w]);
                if (w < warp) off += c;
                tot += c;
            }
            if (spk1 > 0.5f) L1[off + __popc(m1 & ((1u << lane) - 1u))] = j;
            n1 = tot;
        }
        __syncthreads();                                   // B: L1 ready

        // ---- merged gather over L1_t: w11 -> s11 (for t+1), w12 -> h2 part
        float a1 = i1n + bh1;
        float a2 = bh2;
        gather_pair(L1, n1, g_Wt_h12h1, g_Wt_h12h2, j, a1, a2);
        s11 = a1;

        // ---- layer 2
        float h2 = a2 + s22;
        bb2  = ro2 * bb2 + BETA_ * (1.f - ro2) * spk2;
        mem2 = mem2 * alpha2 - bb2 * spk2 + (1.f - alpha2) * h2;
        spk2 = (mem2 - bb2 - BJ0 > 0.f) ? 1.f : 0.f;

        unsigned m2 = __ballot_sync(0xffffffffu, spk2 > 0.5f);
        if (lane == 0) msk2[warp] = m2;
        __syncthreads();                                   // C
        {
            int off = 0, tot = 0;
            #pragma unroll
            for (int w = 0; w < 8; w++) {
                int c = __popc(msk2[w]);
                if (w < warp) off += c;
                tot += c;
            }
            if (spk2 > 0.5f) L2[off + __popc(m2 & ((1u << lane) - 1u))] = j;
            n2 = tot;
        }
        __syncthreads();                                   // D: L2 ready

        // ---- gather over L2_t: w22 -> s22 (for t+1)
        float a3 = 0.f;
        gather_one(L2, n2, g_Wt_h22h2, j, a3);
        s22 = a3;

        // ---- output partials: warp w sums its ascending chunk of L2
        if (lane < DOUT) {
            float po = 0.f;
            const int i0 = (n2 * warp) >> 3;
            const int i1 = (n2 * (warp + 1)) >> 3;
            int i = i0;
            for (; i + 4 <= i1; i += 4) {
                float w0 = g_Wt_h2o[L2[i]     * DOUT + lane];
                float w1 = g_Wt_h2o[L2[i + 1] * DOUT + lane];
                float w2 = g_Wt_h2o[L2[i + 2] * DOUT + lane];
                float w3 = g_Wt_h2o[L2[i + 3] * DOUT + lane];
                po += w0; po += w1; po += w2; po += w3;
            }
            for (; i < i1; i++) po += g_Wt_h2o[L2[i] * DOUT + lane];
            part[warp * DOUT + lane] = po;
        }
        __syncthreads();                                   // E: partials ready

        if (warp == 0) {
            float oin = 0.f;
            if (lane < DOUT) {
                oin = bo;
                #pragma unroll
                for (int w = 0; w < 8; w++) oin += part[w * DOUT + lane];
            }
            mem_o = mem_o * alpha_o + (1.f - alpha_o) * oin;
            float vv = (lane < DOUT) ? mem_o : -1e30f;
            float mx = vv;
            #pragma unroll
            for (int s = 16; s > 0; s >>= 1)
                mx = fmaxf(mx, __shfl_xor_sync(0xffffffffu, mx, s));
            float e = (lane < DOUT) ? expf(vv - mx) : 0.f;
            float sm = e;
            #pragma unroll
            for (int s = 16; s > 0; s >>= 1)
                sm += __shfl_xor_sync(0xffffffffu, sm, s);
            if (lane < DOUT) acc_o += e / sm;
        }
    }

    if (j < DOUT) out[b * DOUT + j] = acc_o;
}

// ---------------------------------------------------------------------------
extern "C" void kernel_launch(void* const* d_in, const int* in_sizes, int n_in,
                              void* d_out, int out_size) {
    const float* x          = (const float*)d_in[0];
    const float* w_i2h1     = (const float*)d_in[1];
    const float* w_h12h1    = (const float*)d_in[2];
    const float* w_h12h2    = (const float*)d_in[3];
    const float* w_h22h2    = (const float*)d_in[4];
    const float* w_h2o      = (const float*)d_in[5];
    const float* b_h1       = (const float*)d_in[6];
    const float* b_h2       = (const float*)d_in[7];
    const float* b_o        = (const float*)d_in[8];
    const float* tau_adp_h1 = (const float*)d_in[9];
    const float* tau_adp_h2 = (const float*)d_in[10];
    const float* tau_m_h1   = (const float*)d_in[11];
    const float* tau_m_h2   = (const float*)d_in[12];
    const float* tau_m_o    = (const float*)d_in[13];

    prep_kernel<<<(H1N * DIN + 255) / 256, 256>>>(w_i2h1, w_h12h1, w_h12h2,
                                                  w_h22h2, w_h2o);
    input_proj_kernel<<<B_ * T_, 256>>>(x);
    recurrent_kernel<<<B_, 256>>>(b_h1, b_h2, b_o,
                                  tau_adp_h1, tau_adp_h2,
                                  tau_m_h1, tau_m_h2, tau_m_o,
                                  (float*)d_out);
}